// round 15
// baseline (speedup 1.0000x reference)
#include <cuda_runtime.h>
#include <cuda.h>
#include <cuda_fp16.h>
#include <math.h>
#include <stdint.h>

// Problem shape (fixed by the dataset)
#define BB 8
#define NN 4096
#define MM 4096
#define CC 128

#define FINF __int_as_float(0x7F800000)

// ---- TMA kernel (2 CTA/SM): tile 128x128, 256 threads, warp tile 64x32 ----
#define T2N 128
#define T2M 128
#define T2_TOTAL 8192          // 32 n-tiles * 32 m-tiles * 8 batches
#define T2_BSL 16384           // B K-slice (128 rows * 128B)
#define T2_ASL 16384           // A K-slice
#define T2_AOFF (2 * T2_BSL)   // 32768
#define T2_ABUF (2 * T2_ASL)   // 32768 per A buffer
#define T2_SCR (T2_AOFF + 2 * T2_ABUF)  // 98304 (2 parity scratch bufs x 4KB)
#define T2_MBAR (T2_SCR + 8192)         // 106496
#define T2_SMEM (T2_MBAR + 64)          // 106560 -> 2 CTAs/SM (213KB < 228KB)

// ---- cp.async fallback (R10, proven 113us) ----
#define TN 128
#define TM 256
#define TT_TOTAL 4096
#define RSB 144
#define ASL 18432
#define BSL 36864
#define ABUF (2 * ASL)
#define BBUF (2 * BSL)
#define AOFF BBUF
#define SCR  (AOFF + 2 * ABUF)
#define SMEM_BYTES (SCR + 4096)

// Scratch (no allocations allowed in kernel_launch)
__device__ float  g_rowmin[BB * NN];
__device__ float  g_colmin[BB * MM];
__device__ float  g_x2[BB * NN];
__device__ float  g_y2[BB * MM];
__device__ double g_acc;
__device__ int    g_done2 = 0;
__device__ __half g_xh[BB * NN * CC];
__device__ __half g_yh[BB * MM * CC];

// One warp per point: fp32 -> fp16 + norm of the ROUNDED values; fused init.
__global__ void convert_norms_kernel(const float* __restrict__ X, const float* __restrict__ Y) {
    int gwarp = (blockIdx.x * blockDim.x + threadIdx.x) >> 5;
    int lane = threadIdx.x & 31;

    if (threadIdx.x < 8) {
        int idx = blockIdx.x * 8 + threadIdx.x;
        if (blockIdx.y) g_colmin[idx] = FINF; else g_rowmin[idx] = FINF;
        if (idx == 0 && blockIdx.y == 0) { g_acc = 0.0; g_done2 = 0; }
    }

    const float* src = blockIdx.y ? Y : X;
    __half* dsth = blockIdx.y ? g_yh : g_xh;
    float* dst2 = blockIdx.y ? g_y2 : g_x2;
    if (gwarp >= BB * NN) return;

    float4 v = ((const float4*)(src + (size_t)gwarp * CC))[lane];
    __half2 h0 = __floats2half2_rn(v.x, v.y);
    __half2 h1 = __floats2half2_rn(v.z, v.w);
    uint2 st;
    st.x = *(const unsigned*)&h0;
    st.y = *(const unsigned*)&h1;
    ((uint2*)(dsth + (size_t)gwarp * CC))[lane] = st;

    float2 b0 = __half22float2(h0), b1 = __half22float2(h1);
    float s = b0.x * b0.x + b0.y * b0.y + b1.x * b1.x + b1.y * b1.y;
#pragma unroll
    for (int off = 16; off > 0; off >>= 1)
        s += __shfl_xor_sync(0xFFFFFFFFu, s, off);
    if (lane == 0) dst2[gwarp] = s;
}

// ---------------- PTX helpers ----------------
__device__ __forceinline__ uint32_t smem_u32(const void* p) {
    return (uint32_t)__cvta_generic_to_shared(p);
}
__device__ __forceinline__ void cp16(uint32_t saddr, const void* gaddr) {
    asm volatile("cp.async.cg.shared.global [%0], [%1], 16;\n" :: "r"(saddr), "l"(gaddr));
}
__device__ __forceinline__ void cp_commit() { asm volatile("cp.async.commit_group;\n"); }
template <int N>
__device__ __forceinline__ void cp_wait() { asm volatile("cp.async.wait_group %0;\n" :: "n"(N)); }

__device__ __forceinline__ void ldsm4(uint32_t& r0, uint32_t& r1, uint32_t& r2, uint32_t& r3,
                                      uint32_t addr) {
    asm volatile("ldmatrix.sync.aligned.m8n8.x4.shared.b16 {%0,%1,%2,%3}, [%4];"
                 : "=r"(r0), "=r"(r1), "=r"(r2), "=r"(r3) : "r"(addr));
}
__device__ __forceinline__ void mma_f16(float& c0, float& c1, float& c2, float& c3,
                                        uint32_t a0, uint32_t a1, uint32_t a2, uint32_t a3,
                                        uint32_t b0, uint32_t b1) {
    asm volatile(
        "mma.sync.aligned.m16n8k16.row.col.f32.f16.f16.f32 "
        "{%0,%1,%2,%3}, {%4,%5,%6,%7}, {%8,%9}, {%0,%1,%2,%3};"
        : "+f"(c0), "+f"(c1), "+f"(c2), "+f"(c3)
        : "r"(a0), "r"(a1), "r"(a2), "r"(a3), "r"(b0), "r"(b1));
}
__device__ __forceinline__ void mbar_init(uint32_t a, uint32_t cnt) {
    asm volatile("mbarrier.init.shared.b64 [%0], %1;" :: "r"(a), "r"(cnt) : "memory");
}
__device__ __forceinline__ void mbar_expect(uint32_t a, uint32_t bytes) {
    asm volatile("mbarrier.arrive.expect_tx.shared.b64 _, [%0], %1;" :: "r"(a), "r"(bytes) : "memory");
}
__device__ __forceinline__ void mbar_wait(uint32_t a, uint32_t parity) {
    asm volatile(
        "{\n\t.reg .pred P1;\n\t"
        "WL%=:\n\t"
        "mbarrier.try_wait.parity.acquire.cta.shared::cta.b64 P1, [%0], %1, 0x989680;\n\t"
        "@P1 bra.uni WD%=;\n\t"
        "bra.uni WL%=;\n\t"
        "WD%=:\n\t}"
        :: "r"(a), "r"(parity) : "memory");
}
__device__ __forceinline__ void tma2d(uint32_t dst, const void* tmap, int x, int y, uint32_t mbar) {
    asm volatile(
        "cp.async.bulk.tensor.2d.shared::cta.global.tile.mbarrier::complete_tx::bytes "
        "[%0], [%1, {%2, %3}], [%4];"
        :: "r"(dst), "l"(tmap), "r"(x), "r"(y), "r"(mbar) : "memory");
}

// ================= TMA persistent kernel, 2 CTA/SM, 16 warps/SM =================
// Tile tt: n-tile = tt&31 (fastest), column cc = tt>>5; m-tile = cc&31, b = cc>>5.
// 256 threads = 8 warps: wn = w>>2 (2 row-halves of 64), wm = w&3 (4 col-slices
// of 32). Warp tile 64x32: mt=4 (m16), nt=4 (n8). acc = 64 regs/thread.
__global__ void __launch_bounds__(256, 2)
chamfer_tma_kernel(const __grid_constant__ CUtensorMap tmX,
                   const __grid_constant__ CUtensorMap tmY) {
    extern __shared__ __align__(1024) char smem[];
    uint32_t sbase = smem_u32(smem);

    const int tid  = threadIdx.x;
    const int lane = tid & 31;
    const int w    = tid >> 5;        // 0..7
    const int g    = lane >> 2;
    const int t    = lane & 3;
    const int wn   = w >> 2;          // 0..1 -> row offset wn*64
    const int wm   = w & 3;           // 0..3 -> col offset wm*32

    const int chunk = (T2_TOTAL + gridDim.x - 1) / gridDim.x;
    const int t0 = blockIdx.x * chunk;
    const int t1 = min(t0 + chunk, T2_TOTAL);
    if (t0 >= T2_TOTAL) return;

    const int arow = lane & 15;
    const int akc  = lane >> 4;
    const int brow = ((lane >> 4) << 3) + (lane & 7);
    const int bkc  = (lane >> 3) & 1;

    if (tid == 0) { mbar_init(sbase + T2_MBAR, 1); mbar_init(sbase + T2_MBAR + 8, 1); }
    __syncthreads();

    int ph[2] = {0, 0};
    float cmin0[4], cmin1[4];   // persist across the column
    float y2a[4], y2b[4];       // y norms, loaded once per column

    for (int tt = t0; tt < t1; tt++) {
        const int cc = tt >> 5;
        const int b  = cc >> 5;
        const int n0 = (tt & 31) * T2N;
        const int m0 = (cc & 31) * T2M;
        const int p  = tt & 1;

        const bool colstart = (tt == t0) || ((tt & 31) == 0);
        if (colstart) {
            if (tid == 0) {
                mbar_expect(sbase + T2_MBAR + p * 8, 2 * T2_BSL + 2 * T2_ASL);
                tma2d(sbase,           &tmY, 0,  b * MM + m0, sbase + T2_MBAR + p * 8);
                tma2d(sbase + T2_BSL,  &tmY, 64, b * MM + m0, sbase + T2_MBAR + p * 8);
                uint32_t abuf = sbase + T2_AOFF + p * T2_ABUF;
                tma2d(abuf,           &tmX, 0,  b * NN + n0, sbase + T2_MBAR + p * 8);
                tma2d(abuf + T2_ASL,  &tmX, 64, b * NN + n0, sbase + T2_MBAR + p * 8);
            }
#pragma unroll
            for (int q = 0; q < 4; q++) { cmin0[q] = FINF; cmin1[q] = FINF; }
#pragma unroll
            for (int nt = 0; nt < 4; nt++) {
                int c0 = m0 + wm * 32 + nt * 8 + 2 * t;
                y2a[nt] = g_y2[(size_t)b * MM + c0];
                y2b[nt] = g_y2[(size_t)b * MM + c0 + 1];
            }
        }
        // prefetch next A within the column
        if (tid == 0 && (tt + 1 < t1) && (((tt + 1) & 31) != 0)) {
            int pn = p ^ 1;
            int nn0 = ((tt + 1) & 31) * T2N;
            uint32_t abuf = sbase + T2_AOFF + pn * T2_ABUF;
            mbar_expect(sbase + T2_MBAR + pn * 8, 2 * T2_ASL);
            tma2d(abuf,          &tmX, 0,  b * NN + nn0, sbase + T2_MBAR + pn * 8);
            tma2d(abuf + T2_ASL, &tmX, 64, b * NN + nn0, sbase + T2_MBAR + pn * 8);
        }

        mbar_wait(sbase + T2_MBAR + p * 8, ph[p]);
        ph[p] ^= 1;

        const uint32_t abase = sbase + T2_AOFF + p * T2_ABUF;

        float acc[4][4][4];
#pragma unroll
        for (int mt = 0; mt < 4; mt++)
#pragma unroll
            for (int nt = 0; nt < 4; nt++)
#pragma unroll
                for (int c = 0; c < 4; c++)
                    acc[mt][nt][c] = 0.0f;

#pragma unroll
        for (int s = 0; s < 2; s++) {
            uint32_t abuf = abase + s * T2_ASL;
            uint32_t bbuf = sbase + s * T2_BSL;
#pragma unroll
            for (int ks = 0; ks < 4; ks++) {
                uint32_t a[4][4], bf[4][2];
#pragma unroll
                for (int mt = 0; mt < 4; mt++) {
                    int r = wn * 64 + mt * 16 + arow;
                    ldsm4(a[mt][0], a[mt][1], a[mt][2], a[mt][3],
                          abuf + r * 128 + (((ks * 2 + akc) ^ (r & 7)) << 4));
                }
#pragma unroll
                for (int pp = 0; pp < 2; pp++) {
                    int r = wm * 32 + pp * 16 + brow;
                    uint32_t r0, r1, r2, r3;
                    ldsm4(r0, r1, r2, r3,
                          bbuf + r * 128 + (((ks * 2 + bkc) ^ (r & 7)) << 4));
                    bf[2 * pp][0] = r0; bf[2 * pp][1] = r1;
                    bf[2 * pp + 1][0] = r2; bf[2 * pp + 1][1] = r3;
                }
#pragma unroll
                for (int mt = 0; mt < 4; mt++)
#pragma unroll
                    for (int nt = 0; nt < 4; nt++)
                        mma_f16(acc[mt][nt][0], acc[mt][nt][1], acc[mt][nt][2], acc[mt][nt][3],
                                a[mt][0], a[mt][1], a[mt][2], a[mt][3],
                                bf[nt][0], bf[nt][1]);
            }
        }

        // Epilogue. C frag: c0=(g,2t) c1=(g,2t+1) c2=(g+8,2t) c3=(g+8,2t+1).
        float rmin0[4], rmin1[4];
#pragma unroll
        for (int mt = 0; mt < 4; mt++) {
            int r0 = n0 + wn * 64 + mt * 16 + g;
            float x2a = g_x2[(size_t)b * NN + r0];
            float x2b = g_x2[(size_t)b * NN + r0 + 8];
            float ra = FINF, rb = FINF;
#pragma unroll
            for (int nt = 0; nt < 4; nt++) {
                float d00 = x2a + y2a[nt] - 2.0f * acc[mt][nt][0];
                float d01 = x2a + y2b[nt] - 2.0f * acc[mt][nt][1];
                float d10 = x2b + y2a[nt] - 2.0f * acc[mt][nt][2];
                float d11 = x2b + y2b[nt] - 2.0f * acc[mt][nt][3];
                ra = fminf(ra, fminf(d00, d01));
                rb = fminf(rb, fminf(d10, d11));
                cmin0[nt] = fminf(cmin0[nt], fminf(d00, d10));
                cmin1[nt] = fminf(cmin1[nt], fminf(d01, d11));
            }
            rmin0[mt] = ra;
            rmin1[mt] = rb;
        }

        // parity-doubled scratch
        float* redr = (float*)(smem + T2_SCR + (tt & 1) * 4096);  // [128][4]
        float* redc = redr + 512;                                 // [128][2]

        // Row mins: reduce across t (lane bits 0,1), flush every tile
#pragma unroll
        for (int mt = 0; mt < 4; mt++) {
#pragma unroll
            for (int off = 1; off <= 2; off <<= 1) {
                rmin0[mt] = fminf(rmin0[mt], __shfl_xor_sync(0xFFFFFFFFu, rmin0[mt], off));
                rmin1[mt] = fminf(rmin1[mt], __shfl_xor_sync(0xFFFFFFFFu, rmin1[mt], off));
            }
        }
        if (t == 0) {
#pragma unroll
            for (int mt = 0; mt < 4; mt++) {
                int r = wn * 64 + mt * 16 + g;
                redr[r * 4 + wm] = rmin0[mt];
                redr[(r + 8) * 4 + wm] = rmin1[mt];
            }
        }

        // Col mins: reduce across g + flush only at column end
        const bool colend = (tt == t1 - 1) || ((tt & 31) == 31);
        if (colend) {
            float c0v[4], c1v[4];
#pragma unroll
            for (int nt = 0; nt < 4; nt++) {
                c0v[nt] = cmin0[nt]; c1v[nt] = cmin1[nt];
#pragma unroll
                for (int off = 4; off <= 16; off <<= 1) {
                    c0v[nt] = fminf(c0v[nt], __shfl_xor_sync(0xFFFFFFFFu, c0v[nt], off));
                    c1v[nt] = fminf(c1v[nt], __shfl_xor_sync(0xFFFFFFFFu, c1v[nt], off));
                }
            }
            if (g == 0) {
#pragma unroll
                for (int nt = 0; nt < 4; nt++) {
                    int c = wm * 32 + nt * 8 + 2 * t;
                    redc[c * 2 + wn] = c0v[nt];
                    redc[(c + 1) * 2 + wn] = c1v[nt];
                }
            }
        }
        __syncthreads();

        if (tid < 128) {
            float rv = fminf(fminf(redr[tid * 4], redr[tid * 4 + 1]),
                             fminf(redr[tid * 4 + 2], redr[tid * 4 + 3]));
            rv = fmaxf(rv, 0.0f);
            atomicMin((int*)&g_rowmin[(size_t)b * NN + n0 + tid], __float_as_int(rv));
        }
        if (colend && tid < 128) {
            float cv = fminf(redc[tid * 2], redc[tid * 2 + 1]);
            cv = fmaxf(cv, 0.0f);
            atomicMin((int*)&g_colmin[(size_t)b * MM + m0 + tid], __float_as_int(cv));
        }
        // scratch parity + mbarrier phases guard reuse
    }
}

// ================= cp.async fallback (R10 kernel, proven 113us) =================
__global__ void __launch_bounds__(256, 1)
chamfer_cp_kernel() {
    extern __shared__ char smem[];
    uint32_t sbase = smem_u32(smem);

    const int tid  = threadIdx.x;
    const int lane = tid & 31;
    const int w    = tid >> 5;
    const int g    = lane >> 2;
    const int t    = lane & 3;
    const int wn   = w >> 2;
    const int wm   = w & 3;

    const int chunk = (TT_TOTAL + gridDim.x - 1) / gridDim.x;
    const int t0 = blockIdx.x * chunk;
    const int t1 = min(t0 + chunk, TT_TOTAL);
    if (t0 >= TT_TOTAL) return;

    const int arow = lane & 15;
    const int akc  = lane >> 4;
    const int brow = ((lane >> 4) << 3) + (lane & 7);
    const int bkc  = (lane >> 3) & 1;

    auto stageA = [&](int tt) {
        int cc = tt >> 5, b = cc >> 4;
        int n0 = (tt & 31) * TN;
        uint32_t abuf = sbase + AOFF + (tt & 1) * ABUF;
        const __half* xb = g_xh + ((size_t)b * NN + n0) * CC;
#pragma unroll
        for (int p = 0; p < 8; p++) {
            int c = p * 256 + tid;
            int s = c >> 10;
            int r = (c & 1023) >> 3, col = c & 7;
            cp16(abuf + s * ASL + r * RSB + col * 16,
                 xb + (size_t)r * CC + s * 64 + col * 8);
        }
    };
    auto stageB = [&](int cc) {
        int b = cc >> 4, m0 = (cc & 15) * TM;
        const __half* yb = g_yh + ((size_t)b * MM + m0) * CC;
#pragma unroll
        for (int p = 0; p < 16; p++) {
            int c = p * 256 + tid;
            int s = c >> 11;
            int r = (c & 2047) >> 3, col = c & 7;
            cp16(sbase + s * BSL + r * RSB + col * 16,
                 yb + (size_t)r * CC + s * 64 + col * 8);
        }
    };

    float cmin0[8], cmin1[8];
    float y2a[8], y2b[8];

    for (int tt = t0; tt < t1; tt++) {
        const int cc = tt >> 5;
        const int b  = cc >> 4;
        const int n0 = (tt & 31) * TN;
        const int m0 = (cc & 15) * TM;

        const bool colstart = (tt == t0) || ((tt & 31) == 0);
        if (colstart) {
            stageB(cc);
            stageA(tt);
            cp_commit();
#pragma unroll
            for (int q = 0; q < 8; q++) { cmin0[q] = FINF; cmin1[q] = FINF; }
#pragma unroll
            for (int nt = 0; nt < 8; nt++) {
                int c0 = m0 + wm * 64 + nt * 8 + 2 * t;
                y2a[nt] = g_y2[(size_t)b * MM + c0];
                y2b[nt] = g_y2[(size_t)b * MM + c0 + 1];
            }
        }
        const bool pref = (tt + 1 < t1) && (((tt + 1) & 31) != 0);
        if (pref) { stageA(tt + 1); cp_commit(); }
        if (pref) cp_wait<1>(); else cp_wait<0>();
        __syncthreads();

        const uint32_t abase = sbase + AOFF + (tt & 1) * ABUF;

        float acc[4][8][4];
#pragma unroll
        for (int mt = 0; mt < 4; mt++)
#pragma unroll
            for (int nt = 0; nt < 8; nt++)
#pragma unroll
                for (int c = 0; c < 4; c++)
                    acc[mt][nt][c] = 0.0f;

#pragma unroll
        for (int s = 0; s < 2; s++) {
            uint32_t abuf = abase + s * ASL;
            uint32_t bbuf = sbase + s * BSL;
#pragma unroll
            for (int ks = 0; ks < 4; ks++) {
                uint32_t a[4][4], bf[8][2];
#pragma unroll
                for (int mt = 0; mt < 4; mt++)
                    ldsm4(a[mt][0], a[mt][1], a[mt][2], a[mt][3],
                          abuf + (wn * 64 + mt * 16 + arow) * RSB + ks * 32 + akc * 16);
#pragma unroll
                for (int p = 0; p < 4; p++) {
                    uint32_t r0, r1, r2, r3;
                    ldsm4(r0, r1, r2, r3,
                          bbuf + (wm * 64 + p * 16 + brow) * RSB + ks * 32 + bkc * 16);
                    bf[2 * p][0] = r0; bf[2 * p][1] = r1;
                    bf[2 * p + 1][0] = r2; bf[2 * p + 1][1] = r3;
                }
#pragma unroll
                for (int mt = 0; mt < 4; mt++)
#pragma unroll
                    for (int nt = 0; nt < 8; nt++)
                        mma_f16(acc[mt][nt][0], acc[mt][nt][1], acc[mt][nt][2], acc[mt][nt][3],
                                a[mt][0], a[mt][1], a[mt][2], a[mt][3],
                                bf[nt][0], bf[nt][1]);
            }
        }

        float rmin0[4], rmin1[4];
#pragma unroll
        for (int mt = 0; mt < 4; mt++) {
            int r0 = n0 + wn * 64 + mt * 16 + g;
            float x2a = g_x2[(size_t)b * NN + r0];
            float x2b = g_x2[(size_t)b * NN + r0 + 8];
            float ra = FINF, rb = FINF;
#pragma unroll
            for (int nt = 0; nt < 8; nt++) {
                float d00 = x2a + y2a[nt] - 2.0f * acc[mt][nt][0];
                float d01 = x2a + y2b[nt] - 2.0f * acc[mt][nt][1];
                float d10 = x2b + y2a[nt] - 2.0f * acc[mt][nt][2];
                float d11 = x2b + y2b[nt] - 2.0f * acc[mt][nt][3];
                ra = fminf(ra, fminf(d00, d01));
                rb = fminf(rb, fminf(d10, d11));
                cmin0[nt] = fminf(cmin0[nt], fminf(d00, d10));
                cmin1[nt] = fminf(cmin1[nt], fminf(d01, d11));
            }
            rmin0[mt] = ra;
            rmin1[mt] = rb;
        }

        float* redr = (float*)(smem + SCR);
        float* redc = redr + 512;

#pragma unroll
        for (int mt = 0; mt < 4; mt++) {
#pragma unroll
            for (int off = 1; off <= 2; off <<= 1) {
                rmin0[mt] = fminf(rmin0[mt], __shfl_xor_sync(0xFFFFFFFFu, rmin0[mt], off));
                rmin1[mt] = fminf(rmin1[mt], __shfl_xor_sync(0xFFFFFFFFu, rmin1[mt], off));
            }
        }
        if (t == 0) {
#pragma unroll
            for (int mt = 0; mt < 4; mt++) {
                int r = wn * 64 + mt * 16 + g;
                redr[r * 4 + wm] = rmin0[mt];
                redr[(r + 8) * 4 + wm] = rmin1[mt];
            }
        }

        const bool colend = (tt == t1 - 1) || ((tt & 31) == 31);
        if (colend) {
            float c0v[8], c1v[8];
#pragma unroll
            for (int nt = 0; nt < 8; nt++) {
                c0v[nt] = cmin0[nt]; c1v[nt] = cmin1[nt];
#pragma unroll
                for (int off = 4; off <= 16; off <<= 1) {
                    c0v[nt] = fminf(c0v[nt], __shfl_xor_sync(0xFFFFFFFFu, c0v[nt], off));
                    c1v[nt] = fminf(c1v[nt], __shfl_xor_sync(0xFFFFFFFFu, c1v[nt], off));
                }
            }
            if (g == 0) {
#pragma unroll
                for (int nt = 0; nt < 8; nt++) {
                    int c = wm * 64 + nt * 8 + 2 * t;
                    redc[c * 2 + wn] = c0v[nt];
                    redc[(c + 1) * 2 + wn] = c1v[nt];
                }
            }
        }
        __syncthreads();

        if (tid < 128) {
            float rv = fminf(fminf(redr[tid * 4], redr[tid * 4 + 1]),
                             fminf(redr[tid * 4 + 2], redr[tid * 4 + 3]));
            rv = fmaxf(rv, 0.0f);
            atomicMin((int*)&g_rowmin[(size_t)b * NN + n0 + tid], __float_as_int(rv));
        }
        if (colend) {
            float cv = fminf(redc[tid * 2], redc[tid * 2 + 1]);
            cv = fmaxf(cv, 0.0f);
            atomicMin((int*)&g_colmin[(size_t)b * MM + m0 + tid], __float_as_int(cv));
        }
        __syncthreads();
    }
}

// Weighted reduction; last block writes the output.
__global__ void partial_final_kernel(const float* __restrict__ w1,
                                     const float* __restrict__ w2,
                                     float* __restrict__ out) {
    __shared__ double sh[256];
    int tid = threadIdx.x;
    int gid = blockIdx.x * 256 + tid;
    int stride = gridDim.x * 256;
    double s = 0.0;
    for (int i = gid; i < BB * NN; i += stride)
        s += (double)w1[i] * sqrtf(g_rowmin[i]);
    for (int i = gid; i < BB * MM; i += stride)
        s += (double)w2[i] * sqrtf(g_colmin[i]);
    sh[tid] = s;
    __syncthreads();
    for (int off = 128; off > 0; off >>= 1) {
        if (tid < off) sh[tid] += sh[tid + off];
        __syncthreads();
    }
    if (tid == 0) {
        atomicAdd(&g_acc, sh[0]);
        __threadfence();
        int done = atomicAdd(&g_done2, 1);
        if (done == (int)gridDim.x - 1) {
            double total = atomicAdd(&g_acc, 0.0);
            out[0] = (float)(total * 0.5);
        }
    }
}

typedef CUresult (*EncodeFn)(CUtensorMap*, CUtensorMapDataType, cuuint32_t, void*,
                             const cuuint64_t*, const cuuint64_t*, const cuuint32_t*,
                             const cuuint32_t*, CUtensorMapInterleave, CUtensorMapSwizzle,
                             CUtensorMapL2promotion, CUtensorMapFloatOOBfill);

extern "C" void kernel_launch(void* const* d_in, const int* in_sizes, int n_in,
                              void* d_out, int out_size) {
    const float* set1 = (const float*)d_in[0];
    const float* set2 = (const float*)d_in[1];
    const float* w1   = (const float*)d_in[2];
    const float* w2   = (const float*)d_in[3];
    float* out = (float*)d_out;

    int nsm = 148;
    cudaDeviceGetAttribute(&nsm, cudaDevAttrMultiProcessorCount, 0);

    dim3 ngrid((BB * NN) / 8, 2, 1);
    convert_norms_kernel<<<ngrid, 256>>>(set1, set2);

    bool tma_ok = false;
    CUtensorMap tmX, tmY;
    {
        EncodeFn enc = nullptr;
        cudaDriverEntryPointQueryResult qr;
        if (cudaGetDriverEntryPoint("cuTensorMapEncodeTiled", (void**)&enc,
                                    cudaEnableDefault, &qr) == cudaSuccess && enc) {
            void *xaddr = nullptr, *yaddr = nullptr;
            cudaGetSymbolAddress(&xaddr, g_xh);
            cudaGetSymbolAddress(&yaddr, g_yh);
            if (xaddr && yaddr) {
                cuuint64_t dims[2] = {128, (cuuint64_t)BB * NN};
                cuuint64_t strides[1] = {CC * 2};
                cuuint32_t boxX[2] = {64, T2N}, boxY[2] = {64, T2M}, es[2] = {1, 1};
                CUresult r1 = enc(&tmX, CU_TENSOR_MAP_DATA_TYPE_UINT16, 2, xaddr,
                                  dims, strides, boxX, es,
                                  CU_TENSOR_MAP_INTERLEAVE_NONE, CU_TENSOR_MAP_SWIZZLE_128B,
                                  CU_TENSOR_MAP_L2_PROMOTION_L2_128B,
                                  CU_TENSOR_MAP_FLOAT_OOB_FILL_NONE);
                CUresult r2 = enc(&tmY, CU_TENSOR_MAP_DATA_TYPE_UINT16, 2, yaddr,
                                  dims, strides, boxY, es,
                                  CU_TENSOR_MAP_INTERLEAVE_NONE, CU_TENSOR_MAP_SWIZZLE_128B,
                                  CU_TENSOR_MAP_L2_PROMOTION_L2_128B,
                                  CU_TENSOR_MAP_FLOAT_OOB_FILL_NONE);
                tma_ok = (r1 == CUDA_SUCCESS) && (r2 == CUDA_SUCCESS);
            }
        }
    }

    if (tma_ok) {
        cudaFuncSetAttribute(chamfer_tma_kernel,
                             cudaFuncAttributeMaxDynamicSharedMemorySize, T2_SMEM);
        chamfer_tma_kernel<<<2 * nsm, 256, T2_SMEM>>>(tmX, tmY);
    } else {
        cudaFuncSetAttribute(chamfer_cp_kernel,
                             cudaFuncAttributeMaxDynamicSharedMemorySize, SMEM_BYTES);
        chamfer_cp_kernel<<<nsm, 256, SMEM_BYTES>>>();
    }

    partial_final_kernel<<<64, 256>>>(w1, w2, out);
}

// round 16
// speedup vs baseline: 1.5924x; 1.5924x over previous
#include <cuda_runtime.h>
#include <cuda.h>
#include <cuda_fp16.h>
#include <math.h>
#include <stdint.h>

// Problem shape (fixed by the dataset)
#define BB 8
#define NN 4096
#define MM 4096
#define CC 128

#define FINF __int_as_float(0x7F800000)

// ---- TMA kernel (2 CTA/SM): tile 128x128, 128 threads (R13 config) ----
#define T2N 128
#define T2M 128
#define T2_TOTAL 8192          // 32 n-tiles * 32 m-tiles * 8 batches
#define T2_BSL 16384           // B K-slice (128 rows * 128B)
#define T2_ASL 16384           // A K-slice
#define T2_AOFF (2 * T2_BSL)   // 32768
#define T2_ABUF (2 * T2_ASL)   // 32768 per A buffer
#define T2_SCR (T2_AOFF + 2 * T2_ABUF)  // 98304 (2 parity scratch bufs x 2KB)
#define T2_MBAR (T2_SCR + 4096)         // 102400
#define T2_SMEM (T2_MBAR + 64)          // 102464 -> 2 CTAs/SM

// ---- cp.async fallback (R10, proven 113us) ----
#define TN 128
#define TM 256
#define TT_TOTAL 4096
#define RSB 144
#define ASL 18432
#define BSL 36864
#define ABUF (2 * ASL)
#define BBUF (2 * BSL)
#define AOFF BBUF
#define SCR  (AOFF + 2 * ABUF)
#define SMEM_BYTES (SCR + 4096)

// Scratch (no allocations allowed in kernel_launch)
__device__ float  g_rowmin[BB * NN];
__device__ float  g_colmin[BB * MM];
__device__ float  g_x2[BB * NN];
__device__ float  g_y2[BB * MM];
__device__ double g_acc;
__device__ int    g_done2 = 0;
__device__ __half g_xh[BB * NN * CC];
__device__ __half g_yh[BB * MM * CC];

// 4 points per warp: fp32 -> fp16 + norm of the ROUNDED values; fused init.
// 4 independent iterations per warp -> 4x MLP vs 1 point/warp.
#define CVT_PPW 4
__global__ void convert_norms_kernel(const float* __restrict__ X, const float* __restrict__ Y) {
    int warp0 = ((blockIdx.x * blockDim.x + threadIdx.x) >> 5) * CVT_PPW;
    int lane = threadIdx.x & 31;

    if (threadIdx.x < 32) {
        int idx = blockIdx.x * 32 + threadIdx.x;
        if (idx < BB * NN) {
            if (blockIdx.y) g_colmin[idx] = FINF; else g_rowmin[idx] = FINF;
        }
        if (idx == 0 && blockIdx.y == 0) { g_acc = 0.0; g_done2 = 0; }
    }

    const float* src = blockIdx.y ? Y : X;
    __half* dsth = blockIdx.y ? g_yh : g_xh;
    float* dst2 = blockIdx.y ? g_y2 : g_x2;

    float4 v[CVT_PPW];
#pragma unroll
    for (int q = 0; q < CVT_PPW; q++)
        v[q] = ((const float4*)(src + (size_t)(warp0 + q) * CC))[lane];

#pragma unroll
    for (int q = 0; q < CVT_PPW; q++) {
        __half2 h0 = __floats2half2_rn(v[q].x, v[q].y);
        __half2 h1 = __floats2half2_rn(v[q].z, v[q].w);
        uint2 st;
        st.x = *(const unsigned*)&h0;
        st.y = *(const unsigned*)&h1;
        ((uint2*)(dsth + (size_t)(warp0 + q) * CC))[lane] = st;

        float2 b0 = __half22float2(h0), b1 = __half22float2(h1);
        float s = b0.x * b0.x + b0.y * b0.y + b1.x * b1.x + b1.y * b1.y;
#pragma unroll
        for (int off = 16; off > 0; off >>= 1)
            s += __shfl_xor_sync(0xFFFFFFFFu, s, off);
        if (lane == 0) dst2[warp0 + q] = s;
    }
}

// ---------------- PTX helpers ----------------
__device__ __forceinline__ uint32_t smem_u32(const void* p) {
    return (uint32_t)__cvta_generic_to_shared(p);
}
__device__ __forceinline__ void cp16(uint32_t saddr, const void* gaddr) {
    asm volatile("cp.async.cg.shared.global [%0], [%1], 16;\n" :: "r"(saddr), "l"(gaddr));
}
__device__ __forceinline__ void cp_commit() { asm volatile("cp.async.commit_group;\n"); }
template <int N>
__device__ __forceinline__ void cp_wait() { asm volatile("cp.async.wait_group %0;\n" :: "n"(N)); }

__device__ __forceinline__ void ldsm4(uint32_t& r0, uint32_t& r1, uint32_t& r2, uint32_t& r3,
                                      uint32_t addr) {
    asm volatile("ldmatrix.sync.aligned.m8n8.x4.shared.b16 {%0,%1,%2,%3}, [%4];"
                 : "=r"(r0), "=r"(r1), "=r"(r2), "=r"(r3) : "r"(addr));
}
__device__ __forceinline__ void mma_f16(float& c0, float& c1, float& c2, float& c3,
                                        uint32_t a0, uint32_t a1, uint32_t a2, uint32_t a3,
                                        uint32_t b0, uint32_t b1) {
    asm volatile(
        "mma.sync.aligned.m16n8k16.row.col.f32.f16.f16.f32 "
        "{%0,%1,%2,%3}, {%4,%5,%6,%7}, {%8,%9}, {%0,%1,%2,%3};"
        : "+f"(c0), "+f"(c1), "+f"(c2), "+f"(c3)
        : "r"(a0), "r"(a1), "r"(a2), "r"(a3), "r"(b0), "r"(b1));
}
__device__ __forceinline__ void mbar_init(uint32_t a, uint32_t cnt) {
    asm volatile("mbarrier.init.shared.b64 [%0], %1;" :: "r"(a), "r"(cnt) : "memory");
}
__device__ __forceinline__ void mbar_expect(uint32_t a, uint32_t bytes) {
    asm volatile("mbarrier.arrive.expect_tx.shared.b64 _, [%0], %1;" :: "r"(a), "r"(bytes) : "memory");
}
__device__ __forceinline__ void mbar_wait(uint32_t a, uint32_t parity) {
    asm volatile(
        "{\n\t.reg .pred P1;\n\t"
        "WL%=:\n\t"
        "mbarrier.try_wait.parity.acquire.cta.shared::cta.b64 P1, [%0], %1, 0x989680;\n\t"
        "@P1 bra.uni WD%=;\n\t"
        "bra.uni WL%=;\n\t"
        "WD%=:\n\t}"
        :: "r"(a), "r"(parity) : "memory");
}
__device__ __forceinline__ void tma2d(uint32_t dst, const void* tmap, int x, int y, uint32_t mbar) {
    asm volatile(
        "cp.async.bulk.tensor.2d.shared::cta.global.tile.mbarrier::complete_tx::bytes "
        "[%0], [%1, {%2, %3}], [%4];"
        :: "r"(dst), "l"(tmap), "r"(x), "r"(y), "r"(mbar) : "memory");
}

// ================= TMA persistent kernel, 2 CTA/SM (exact R13 config) =================
// Tile tt: n-tile = tt&31 (fastest), column cc = tt>>5; m-tile = cc&31, b = cc>>5.
// B (128 pts) resident per column; A double-buffered via TMA + mbarrier.
// 128 threads = 4 warps in 2x2; warp tile 64x64 (mt=4, nt=8).
__global__ void __launch_bounds__(128)
chamfer_tma_kernel(const __grid_constant__ CUtensorMap tmX,
                   const __grid_constant__ CUtensorMap tmY) {
    extern __shared__ __align__(1024) char smem[];
    uint32_t sbase = smem_u32(smem);

    const int tid  = threadIdx.x;
    const int lane = tid & 31;
    const int w    = tid >> 5;        // 0..3
    const int g    = lane >> 2;
    const int t    = lane & 3;
    const int wn   = w >> 1;          // 0..1 -> row half
    const int wm   = w & 1;           // 0..1 -> col half

    const int chunk = (T2_TOTAL + gridDim.x - 1) / gridDim.x;
    const int t0 = blockIdx.x * chunk;
    const int t1 = min(t0 + chunk, T2_TOTAL);
    if (t0 >= T2_TOTAL) return;

    const int arow = lane & 15;
    const int akc  = lane >> 4;
    const int brow = ((lane >> 4) << 3) + (lane & 7);
    const int bkc  = (lane >> 3) & 1;

    if (tid == 0) { mbar_init(sbase + T2_MBAR, 1); mbar_init(sbase + T2_MBAR + 8, 1); }
    __syncthreads();

    int ph[2] = {0, 0};
    float cmin0[8], cmin1[8];
    float y2a[8], y2b[8];

    for (int tt = t0; tt < t1; tt++) {
        const int cc = tt >> 5;
        const int b  = cc >> 5;
        const int n0 = (tt & 31) * T2N;
        const int m0 = (cc & 31) * T2M;
        const int p  = tt & 1;

        const bool colstart = (tt == t0) || ((tt & 31) == 0);
        if (colstart) {
            if (tid == 0) {
                mbar_expect(sbase + T2_MBAR + p * 8, 2 * T2_BSL + 2 * T2_ASL);
                tma2d(sbase,           &tmY, 0,  b * MM + m0, sbase + T2_MBAR + p * 8);
                tma2d(sbase + T2_BSL,  &tmY, 64, b * MM + m0, sbase + T2_MBAR + p * 8);
                uint32_t abuf = sbase + T2_AOFF + p * T2_ABUF;
                tma2d(abuf,           &tmX, 0,  b * NN + n0, sbase + T2_MBAR + p * 8);
                tma2d(abuf + T2_ASL,  &tmX, 64, b * NN + n0, sbase + T2_MBAR + p * 8);
            }
#pragma unroll
            for (int q = 0; q < 8; q++) { cmin0[q] = FINF; cmin1[q] = FINF; }
#pragma unroll
            for (int nt = 0; nt < 8; nt++) {
                int c0 = m0 + wm * 64 + nt * 8 + 2 * t;
                y2a[nt] = g_y2[(size_t)b * MM + c0];
                y2b[nt] = g_y2[(size_t)b * MM + c0 + 1];
            }
        }
        // prefetch next A within the column
        if (tid == 0 && (tt + 1 < t1) && (((tt + 1) & 31) != 0)) {
            int pn = p ^ 1;
            int nn0 = ((tt + 1) & 31) * T2N;
            uint32_t abuf = sbase + T2_AOFF + pn * T2_ABUF;
            mbar_expect(sbase + T2_MBAR + pn * 8, 2 * T2_ASL);
            tma2d(abuf,          &tmX, 0,  b * NN + nn0, sbase + T2_MBAR + pn * 8);
            tma2d(abuf + T2_ASL, &tmX, 64, b * NN + nn0, sbase + T2_MBAR + pn * 8);
        }

        mbar_wait(sbase + T2_MBAR + p * 8, ph[p]);
        ph[p] ^= 1;

        const uint32_t abase = sbase + T2_AOFF + p * T2_ABUF;

        float acc[4][8][4];
#pragma unroll
        for (int mt = 0; mt < 4; mt++)
#pragma unroll
            for (int nt = 0; nt < 8; nt++)
#pragma unroll
                for (int c = 0; c < 4; c++)
                    acc[mt][nt][c] = 0.0f;

#pragma unroll
        for (int s = 0; s < 2; s++) {
            uint32_t abuf = abase + s * T2_ASL;
            uint32_t bbuf = sbase + s * T2_BSL;
#pragma unroll
            for (int ks = 0; ks < 4; ks++) {
                uint32_t a[4][4], bf[8][2];
#pragma unroll
                for (int mt = 0; mt < 4; mt++) {
                    int r = wn * 64 + mt * 16 + arow;
                    ldsm4(a[mt][0], a[mt][1], a[mt][2], a[mt][3],
                          abuf + r * 128 + (((ks * 2 + akc) ^ (r & 7)) << 4));
                }
#pragma unroll
                for (int pp = 0; pp < 4; pp++) {
                    int r = wm * 64 + pp * 16 + brow;
                    uint32_t r0, r1, r2, r3;
                    ldsm4(r0, r1, r2, r3,
                          bbuf + r * 128 + (((ks * 2 + bkc) ^ (r & 7)) << 4));
                    bf[2 * pp][0] = r0; bf[2 * pp][1] = r1;
                    bf[2 * pp + 1][0] = r2; bf[2 * pp + 1][1] = r3;
                }
#pragma unroll
                for (int mt = 0; mt < 4; mt++)
#pragma unroll
                    for (int nt = 0; nt < 8; nt++)
                        mma_f16(acc[mt][nt][0], acc[mt][nt][1], acc[mt][nt][2], acc[mt][nt][3],
                                a[mt][0], a[mt][1], a[mt][2], a[mt][3],
                                bf[nt][0], bf[nt][1]);
            }
        }

        // Epilogue. C frag: c0=(g,2t) c1=(g,2t+1) c2=(g+8,2t) c3=(g+8,2t+1).
        float rmin0[4], rmin1[4];
#pragma unroll
        for (int mt = 0; mt < 4; mt++) {
            int r0 = n0 + wn * 64 + mt * 16 + g;
            float x2a = g_x2[(size_t)b * NN + r0];
            float x2b = g_x2[(size_t)b * NN + r0 + 8];
            float ra = FINF, rb = FINF;
#pragma unroll
            for (int nt = 0; nt < 8; nt++) {
                float d00 = x2a + y2a[nt] - 2.0f * acc[mt][nt][0];
                float d01 = x2a + y2b[nt] - 2.0f * acc[mt][nt][1];
                float d10 = x2b + y2a[nt] - 2.0f * acc[mt][nt][2];
                float d11 = x2b + y2b[nt] - 2.0f * acc[mt][nt][3];
                ra = fminf(ra, fminf(d00, d01));
                rb = fminf(rb, fminf(d10, d11));
                cmin0[nt] = fminf(cmin0[nt], fminf(d00, d10));
                cmin1[nt] = fminf(cmin1[nt], fminf(d01, d11));
            }
            rmin0[mt] = ra;
            rmin1[mt] = rb;
        }

        // parity-doubled scratch: one __syncthreads per tile
        float* redr = (float*)(smem + T2_SCR + (tt & 1) * 2048);  // [128][2]
        float* redc = redr + 256;                                 // [128][2]

        // Row mins: flush every tile (16 shfl)
#pragma unroll
        for (int mt = 0; mt < 4; mt++) {
#pragma unroll
            for (int off = 1; off <= 2; off <<= 1) {
                rmin0[mt] = fminf(rmin0[mt], __shfl_xor_sync(0xFFFFFFFFu, rmin0[mt], off));
                rmin1[mt] = fminf(rmin1[mt], __shfl_xor_sync(0xFFFFFFFFu, rmin1[mt], off));
            }
        }
        if (t == 0) {
#pragma unroll
            for (int mt = 0; mt < 4; mt++) {
                int r = wn * 64 + mt * 16 + g;
                redr[r * 2 + wm] = rmin0[mt];
                redr[(r + 8) * 2 + wm] = rmin1[mt];
            }
        }

        // Col mins: flush at column end only
        const bool colend = (tt == t1 - 1) || ((tt & 31) == 31);
        if (colend) {
            float c0v[8], c1v[8];
#pragma unroll
            for (int nt = 0; nt < 8; nt++) {
                c0v[nt] = cmin0[nt]; c1v[nt] = cmin1[nt];
#pragma unroll
                for (int off = 4; off <= 16; off <<= 1) {
                    c0v[nt] = fminf(c0v[nt], __shfl_xor_sync(0xFFFFFFFFu, c0v[nt], off));
                    c1v[nt] = fminf(c1v[nt], __shfl_xor_sync(0xFFFFFFFFu, c1v[nt], off));
                }
            }
            if (g == 0) {
#pragma unroll
                for (int nt = 0; nt < 8; nt++) {
                    int c = wm * 64 + nt * 8 + 2 * t;
                    redc[c * 2 + wn] = c0v[nt];
                    redc[(c + 1) * 2 + wn] = c1v[nt];
                }
            }
        }
        __syncthreads();

        {
            float rv = fminf(redr[tid * 2], redr[tid * 2 + 1]);
            rv = fmaxf(rv, 0.0f);
            atomicMin((int*)&g_rowmin[(size_t)b * NN + n0 + tid], __float_as_int(rv));
        }
        if (colend) {
            float cv = fminf(redc[tid * 2], redc[tid * 2 + 1]);
            cv = fmaxf(cv, 0.0f);
            atomicMin((int*)&g_colmin[(size_t)b * MM + m0 + tid], __float_as_int(cv));
        }
        // scratch parity + mbarrier phases guard reuse
    }
}

// ================= cp.async fallback (R10 kernel, proven 113us) =================
__global__ void __launch_bounds__(256, 1)
chamfer_cp_kernel() {
    extern __shared__ char smem[];
    uint32_t sbase = smem_u32(smem);

    const int tid  = threadIdx.x;
    const int lane = tid & 31;
    const int w    = tid >> 5;
    const int g    = lane >> 2;
    const int t    = lane & 3;
    const int wn   = w >> 2;
    const int wm   = w & 3;

    const int chunk = (TT_TOTAL + gridDim.x - 1) / gridDim.x;
    const int t0 = blockIdx.x * chunk;
    const int t1 = min(t0 + chunk, TT_TOTAL);
    if (t0 >= TT_TOTAL) return;

    const int arow = lane & 15;
    const int akc  = lane >> 4;
    const int brow = ((lane >> 4) << 3) + (lane & 7);
    const int bkc  = (lane >> 3) & 1;

    auto stageA = [&](int tt) {
        int cc = tt >> 5, b = cc >> 4;
        int n0 = (tt & 31) * TN;
        uint32_t abuf = sbase + AOFF + (tt & 1) * ABUF;
        const __half* xb = g_xh + ((size_t)b * NN + n0) * CC;
#pragma unroll
        for (int p = 0; p < 8; p++) {
            int c = p * 256 + tid;
            int s = c >> 10;
            int r = (c & 1023) >> 3, col = c & 7;
            cp16(abuf + s * ASL + r * RSB + col * 16,
                 xb + (size_t)r * CC + s * 64 + col * 8);
        }
    };
    auto stageB = [&](int cc) {
        int b = cc >> 4, m0 = (cc & 15) * TM;
        const __half* yb = g_yh + ((size_t)b * MM + m0) * CC;
#pragma unroll
        for (int p = 0; p < 16; p++) {
            int c = p * 256 + tid;
            int s = c >> 11;
            int r = (c & 2047) >> 3, col = c & 7;
            cp16(sbase + s * BSL + r * RSB + col * 16,
                 yb + (size_t)r * CC + s * 64 + col * 8);
        }
    };

    float cmin0[8], cmin1[8];
    float y2a[8], y2b[8];

    for (int tt = t0; tt < t1; tt++) {
        const int cc = tt >> 5;
        const int b  = cc >> 4;
        const int n0 = (tt & 31) * TN;
        const int m0 = (cc & 15) * TM;

        const bool colstart = (tt == t0) || ((tt & 31) == 0);
        if (colstart) {
            stageB(cc);
            stageA(tt);
            cp_commit();
#pragma unroll
            for (int q = 0; q < 8; q++) { cmin0[q] = FINF; cmin1[q] = FINF; }
#pragma unroll
            for (int nt = 0; nt < 8; nt++) {
                int c0 = m0 + wm * 64 + nt * 8 + 2 * t;
                y2a[nt] = g_y2[(size_t)b * MM + c0];
                y2b[nt] = g_y2[(size_t)b * MM + c0 + 1];
            }
        }
        const bool pref = (tt + 1 < t1) && (((tt + 1) & 31) != 0);
        if (pref) { stageA(tt + 1); cp_commit(); }
        if (pref) cp_wait<1>(); else cp_wait<0>();
        __syncthreads();

        const uint32_t abase = sbase + AOFF + (tt & 1) * ABUF;

        float acc[4][8][4];
#pragma unroll
        for (int mt = 0; mt < 4; mt++)
#pragma unroll
            for (int nt = 0; nt < 8; nt++)
#pragma unroll
                for (int c = 0; c < 4; c++)
                    acc[mt][nt][c] = 0.0f;

#pragma unroll
        for (int s = 0; s < 2; s++) {
            uint32_t abuf = abase + s * ASL;
            uint32_t bbuf = sbase + s * BSL;
#pragma unroll
            for (int ks = 0; ks < 4; ks++) {
                uint32_t a[4][4], bf[8][2];
#pragma unroll
                for (int mt = 0; mt < 4; mt++)
                    ldsm4(a[mt][0], a[mt][1], a[mt][2], a[mt][3],
                          abuf + (wn * 64 + mt * 16 + arow) * RSB + ks * 32 + akc * 16);
#pragma unroll
                for (int p = 0; p < 4; p++) {
                    uint32_t r0, r1, r2, r3;
                    ldsm4(r0, r1, r2, r3,
                          bbuf + (wm * 64 + p * 16 + brow) * RSB + ks * 32 + bkc * 16);
                    bf[2 * p][0] = r0; bf[2 * p][1] = r1;
                    bf[2 * p + 1][0] = r2; bf[2 * p + 1][1] = r3;
                }
#pragma unroll
                for (int mt = 0; mt < 4; mt++)
#pragma unroll
                    for (int nt = 0; nt < 8; nt++)
                        mma_f16(acc[mt][nt][0], acc[mt][nt][1], acc[mt][nt][2], acc[mt][nt][3],
                                a[mt][0], a[mt][1], a[mt][2], a[mt][3],
                                bf[nt][0], bf[nt][1]);
            }
        }

        float rmin0[4], rmin1[4];
#pragma unroll
        for (int mt = 0; mt < 4; mt++) {
            int r0 = n0 + wn * 64 + mt * 16 + g;
            float x2a = g_x2[(size_t)b * NN + r0];
            float x2b = g_x2[(size_t)b * NN + r0 + 8];
            float ra = FINF, rb = FINF;
#pragma unroll
            for (int nt = 0; nt < 8; nt++) {
                float d00 = x2a + y2a[nt] - 2.0f * acc[mt][nt][0];
                float d01 = x2a + y2b[nt] - 2.0f * acc[mt][nt][1];
                float d10 = x2b + y2a[nt] - 2.0f * acc[mt][nt][2];
                float d11 = x2b + y2b[nt] - 2.0f * acc[mt][nt][3];
                ra = fminf(ra, fminf(d00, d01));
                rb = fminf(rb, fminf(d10, d11));
                cmin0[nt] = fminf(cmin0[nt], fminf(d00, d10));
                cmin1[nt] = fminf(cmin1[nt], fminf(d01, d11));
            }
            rmin0[mt] = ra;
            rmin1[mt] = rb;
        }

        float* redr = (float*)(smem + SCR);
        float* redc = redr + 512;

#pragma unroll
        for (int mt = 0; mt < 4; mt++) {
#pragma unroll
            for (int off = 1; off <= 2; off <<= 1) {
                rmin0[mt] = fminf(rmin0[mt], __shfl_xor_sync(0xFFFFFFFFu, rmin0[mt], off));
                rmin1[mt] = fminf(rmin1[mt], __shfl_xor_sync(0xFFFFFFFFu, rmin1[mt], off));
            }
        }
        if (t == 0) {
#pragma unroll
            for (int mt = 0; mt < 4; mt++) {
                int r = wn * 64 + mt * 16 + g;
                redr[r * 4 + wm] = rmin0[mt];
                redr[(r + 8) * 4 + wm] = rmin1[mt];
            }
        }

        const bool colend = (tt == t1 - 1) || ((tt & 31) == 31);
        if (colend) {
            float c0v[8], c1v[8];
#pragma unroll
            for (int nt = 0; nt < 8; nt++) {
                c0v[nt] = cmin0[nt]; c1v[nt] = cmin1[nt];
#pragma unroll
                for (int off = 4; off <= 16; off <<= 1) {
                    c0v[nt] = fminf(c0v[nt], __shfl_xor_sync(0xFFFFFFFFu, c0v[nt], off));
                    c1v[nt] = fminf(c1v[nt], __shfl_xor_sync(0xFFFFFFFFu, c1v[nt], off));
                }
            }
            if (g == 0) {
#pragma unroll
                for (int nt = 0; nt < 8; nt++) {
                    int c = wm * 64 + nt * 8 + 2 * t;
                    redc[c * 2 + wn] = c0v[nt];
                    redc[(c + 1) * 2 + wn] = c1v[nt];
                }
            }
        }
        __syncthreads();

        if (tid < 128) {
            float rv = fminf(fminf(redr[tid * 4], redr[tid * 4 + 1]),
                             fminf(redr[tid * 4 + 2], redr[tid * 4 + 3]));
            rv = fmaxf(rv, 0.0f);
            atomicMin((int*)&g_rowmin[(size_t)b * NN + n0 + tid], __float_as_int(rv));
        }
        if (colend) {
            float cv = fminf(redc[tid * 2], redc[tid * 2 + 1]);
            cv = fmaxf(cv, 0.0f);
            atomicMin((int*)&g_colmin[(size_t)b * MM + m0 + tid], __float_as_int(cv));
        }
        __syncthreads();
    }
}

// Weighted reduction; last block writes the output.
__global__ void partial_final_kernel(const float* __restrict__ w1,
                                     const float* __restrict__ w2,
                                     float* __restrict__ out) {
    __shared__ double sh[256];
    int tid = threadIdx.x;
    int gid = blockIdx.x * 256 + tid;
    int stride = gridDim.x * 256;
    double s = 0.0;
    for (int i = gid; i < BB * NN; i += stride)
        s += (double)w1[i] * sqrtf(g_rowmin[i]);
    for (int i = gid; i < BB * MM; i += stride)
        s += (double)w2[i] * sqrtf(g_colmin[i]);
    sh[tid] = s;
    __syncthreads();
    for (int off = 128; off > 0; off >>= 1) {
        if (tid < off) sh[tid] += sh[tid + off];
        __syncthreads();
    }
    if (tid == 0) {
        atomicAdd(&g_acc, sh[0]);
        __threadfence();
        int done = atomicAdd(&g_done2, 1);
        if (done == (int)gridDim.x - 1) {
            double total = atomicAdd(&g_acc, 0.0);
            out[0] = (float)(total * 0.5);
        }
    }
}

typedef CUresult (*EncodeFn)(CUtensorMap*, CUtensorMapDataType, cuuint32_t, void*,
                             const cuuint64_t*, const cuuint64_t*, const cuuint32_t*,
                             const cuuint32_t*, CUtensorMapInterleave, CUtensorMapSwizzle,
                             CUtensorMapL2promotion, CUtensorMapFloatOOBfill);

extern "C" void kernel_launch(void* const* d_in, const int* in_sizes, int n_in,
                              void* d_out, int out_size) {
    const float* set1 = (const float*)d_in[0];
    const float* set2 = (const float*)d_in[1];
    const float* w1   = (const float*)d_in[2];
    const float* w2   = (const float*)d_in[3];
    float* out = (float*)d_out;

    int nsm = 148;
    cudaDeviceGetAttribute(&nsm, cudaDevAttrMultiProcessorCount, 0);

    dim3 ngrid((BB * NN) / (8 * CVT_PPW), 2, 1);
    convert_norms_kernel<<<ngrid, 256>>>(set1, set2);

    bool tma_ok = false;
    CUtensorMap tmX, tmY;
    {
        EncodeFn enc = nullptr;
        cudaDriverEntryPointQueryResult qr;
        if (cudaGetDriverEntryPoint("cuTensorMapEncodeTiled", (void**)&enc,
                                    cudaEnableDefault, &qr) == cudaSuccess && enc) {
            void *xaddr = nullptr, *yaddr = nullptr;
            cudaGetSymbolAddress(&xaddr, g_xh);
            cudaGetSymbolAddress(&yaddr, g_yh);
            if (xaddr && yaddr) {
                cuuint64_t dims[2] = {128, (cuuint64_t)BB * NN};
                cuuint64_t strides[1] = {CC * 2};
                cuuint32_t boxX[2] = {64, T2N}, boxY[2] = {64, T2M}, es[2] = {1, 1};
                CUresult r1 = enc(&tmX, CU_TENSOR_MAP_DATA_TYPE_UINT16, 2, xaddr,
                                  dims, strides, boxX, es,
                                  CU_TENSOR_MAP_INTERLEAVE_NONE, CU_TENSOR_MAP_SWIZZLE_128B,
                                  CU_TENSOR_MAP_L2_PROMOTION_L2_128B,
                                  CU_TENSOR_MAP_FLOAT_OOB_FILL_NONE);
                CUresult r2 = enc(&tmY, CU_TENSOR_MAP_DATA_TYPE_UINT16, 2, yaddr,
                                  dims, strides, boxY, es,
                                  CU_TENSOR_MAP_INTERLEAVE_NONE, CU_TENSOR_MAP_SWIZZLE_128B,
                                  CU_TENSOR_MAP_L2_PROMOTION_L2_128B,
                                  CU_TENSOR_MAP_FLOAT_OOB_FILL_NONE);
                tma_ok = (r1 == CUDA_SUCCESS) && (r2 == CUDA_SUCCESS);
            }
        }
    }

    if (tma_ok) {
        cudaFuncSetAttribute(chamfer_tma_kernel,
                             cudaFuncAttributeMaxDynamicSharedMemorySize, T2_SMEM);
        chamfer_tma_kernel<<<2 * nsm, 128, T2_SMEM>>>(tmX, tmY);
    } else {
        cudaFuncSetAttribute(chamfer_cp_kernel,
                             cudaFuncAttributeMaxDynamicSharedMemorySize, SMEM_BYTES);
        chamfer_cp_kernel<<<nsm, 256, SMEM_BYTES>>>();
    }

    partial_final_kernel<<<64, 256>>>(w1, w2, out);
}